// round 1
// baseline (speedup 1.0000x reference)
#include <cuda_runtime.h>
#include <math.h>

#define N_NODESC 100000
#define N_EDGESC 500000
#define HIDC 128
#define NODE_INC 16

// Scratch (no allocations allowed) — ping-pong node features + aggregation buffer.
__device__ float g_h [N_NODESC * HIDC];
__device__ float g_hn[N_NODESC * HIDC];
__device__ float g_aggr[N_NODESC * HIDC];

__device__ __forceinline__ float4 ld4(const float* p) {
    return *reinterpret_cast<const float4*>(p);
}
__device__ __forceinline__ void st4(float* p, float4 v) {
    *reinterpret_cast<float4*>(p) = v;
}
__device__ __forceinline__ float eluf(float x) {
    return x > 0.f ? x : expm1f(x);
}
__device__ __forceinline__ float4 elu4(float4 v) {
    v.x = eluf(v.x); v.y = eluf(v.y); v.z = eluf(v.z); v.w = eluf(v.w);
    return v;
}

// ---------------------------------------------------------------------------
// Layer-0 edge messages: aggr16[dst] += relu(x[src] + ea*We0 + be0), 16 feats.
// One thread per (edge, feature).
// ---------------------------------------------------------------------------
__global__ void edge_layer0(const float* __restrict__ x, const int* __restrict__ ei,
                            const float* __restrict__ ea, const float* __restrict__ We,
                            const float* __restrict__ be, float* __restrict__ aggr)
{
    int gid = blockIdx.x * blockDim.x + threadIdx.x;
    int e = gid >> 4;
    int f = gid & 15;
    if (e >= N_EDGESC) return;
    int src = ei[e];
    int dst = ei[N_EDGESC + e];
    float m = x[src * NODE_INC + f] + ea[e] * We[f] + be[f];
    m = fmaxf(m, 0.f);
    atomicAdd(&aggr[dst * NODE_INC + f], m);
}

// ---------------------------------------------------------------------------
// HID edge messages: aggr[dst] += relu(h[src] + ea*We + be), 128 feats.
// One warp per edge; lane handles 4 contiguous features (float4).
// ---------------------------------------------------------------------------
__global__ void edge_msg(const float* __restrict__ h, const int* __restrict__ ei,
                         const float* __restrict__ ea, const float* __restrict__ We,
                         const float* __restrict__ be, float* __restrict__ aggr)
{
    int warp = (blockIdx.x * blockDim.x + threadIdx.x) >> 5;
    int lane = threadIdx.x & 31;
    if (warp >= N_EDGESC) return;
    int e = warp;
    int src = ei[e];
    int dst = ei[N_EDGESC + e];
    float w = ea[e];

    float4 hv = ld4(&h[src * HIDC + lane * 4]);
    float4 wv = ld4(&We[lane * 4]);
    float4 bv = ld4(&be[lane * 4]);
    float4 m;
    m.x = fmaxf(fmaf(w, wv.x, hv.x) + bv.x, 0.f);
    m.y = fmaxf(fmaf(w, wv.y, hv.y) + bv.y, 0.f);
    m.z = fmaxf(fmaf(w, wv.z, hv.z) + bv.z, 0.f);
    m.w = fmaxf(fmaf(w, wv.w, hv.w) + bv.w, 0.f);

    float* ap = &aggr[dst * HIDC + lane * 4];
    atomicAdd(ap + 0, m.x);
    atomicAdd(ap + 1, m.y);
    atomicAdd(ap + 2, m.z);
    atomicAdd(ap + 3, m.w);
}

// ---------------------------------------------------------------------------
// Node MLP: hout = elu( elu((xin + aggr) @ W1 + b1) @ W2 + b2 )
// KIN = input width (16 for layer 0, 128 for stacked layers).
// Block = 256 threads = 8 warps; each warp owns 4 nodes; lane owns 4 output
// columns (lane*4 .. lane*4+3). Inputs staged in smem, broadcast via LDS.128;
// weight rows streamed via LDG.128 (L1-resident).
// ---------------------------------------------------------------------------
template <int KIN>
__global__ void node_mlp(const float* __restrict__ xin, const float* __restrict__ aggr,
                         const float* __restrict__ W1, const float* __restrict__ b1,
                         const float* __restrict__ W2, const float* __restrict__ b2,
                         float* __restrict__ hout)
{
    __shared__ float s_in[32 * KIN];
    __shared__ float s_t [32 * HIDC];

    int tid = threadIdx.x;
    int nb  = blockIdx.x * 32;

    for (int i = tid; i < 32 * KIN; i += 256) {
        int node = i / KIN;
        int k    = i % KIN;
        int gi   = (nb + node) * KIN + k;
        s_in[i] = xin[gi] + aggr[gi];
    }
    __syncthreads();

    int w    = tid >> 5;
    int lane = tid & 31;
    const float* sin0 = &s_in[(w * 4 + 0) * KIN];
    const float* sin1 = &s_in[(w * 4 + 1) * KIN];
    const float* sin2 = &s_in[(w * 4 + 2) * KIN];
    const float* sin3 = &s_in[(w * 4 + 3) * KIN];

    // Phase 1: t = elu(in @ W1 + b1)
    float4 bv = ld4(&b1[lane * 4]);
    float4 acc0 = bv, acc1 = bv, acc2 = bv, acc3 = bv;
    for (int kg = 0; kg < KIN / 4; kg++) {
        float4 a0 = ld4(&sin0[kg * 4]);
        float4 a1 = ld4(&sin1[kg * 4]);
        float4 a2 = ld4(&sin2[kg * 4]);
        float4 a3 = ld4(&sin3[kg * 4]);
        const float* pa0 = (const float*)&a0;
        const float* pa1 = (const float*)&a1;
        const float* pa2 = (const float*)&a2;
        const float* pa3 = (const float*)&a3;
        #pragma unroll
        for (int kk = 0; kk < 4; kk++) {
            float4 wr = ld4(&W1[(kg * 4 + kk) * HIDC + lane * 4]);
            acc0.x = fmaf(pa0[kk], wr.x, acc0.x); acc0.y = fmaf(pa0[kk], wr.y, acc0.y);
            acc0.z = fmaf(pa0[kk], wr.z, acc0.z); acc0.w = fmaf(pa0[kk], wr.w, acc0.w);
            acc1.x = fmaf(pa1[kk], wr.x, acc1.x); acc1.y = fmaf(pa1[kk], wr.y, acc1.y);
            acc1.z = fmaf(pa1[kk], wr.z, acc1.z); acc1.w = fmaf(pa1[kk], wr.w, acc1.w);
            acc2.x = fmaf(pa2[kk], wr.x, acc2.x); acc2.y = fmaf(pa2[kk], wr.y, acc2.y);
            acc2.z = fmaf(pa2[kk], wr.z, acc2.z); acc2.w = fmaf(pa2[kk], wr.w, acc2.w);
            acc3.x = fmaf(pa3[kk], wr.x, acc3.x); acc3.y = fmaf(pa3[kk], wr.y, acc3.y);
            acc3.z = fmaf(pa3[kk], wr.z, acc3.z); acc3.w = fmaf(pa3[kk], wr.w, acc3.w);
        }
    }

    float* st0 = &s_t[(w * 4 + 0) * HIDC];
    float* st1 = &s_t[(w * 4 + 1) * HIDC];
    float* st2 = &s_t[(w * 4 + 2) * HIDC];
    float* st3 = &s_t[(w * 4 + 3) * HIDC];
    st4(&st0[lane * 4], elu4(acc0));
    st4(&st1[lane * 4], elu4(acc1));
    st4(&st2[lane * 4], elu4(acc2));
    st4(&st3[lane * 4], elu4(acc3));
    __syncwarp();

    // Phase 2: out = elu(t @ W2 + b2)
    float4 bv2 = ld4(&b2[lane * 4]);
    acc0 = bv2; acc1 = bv2; acc2 = bv2; acc3 = bv2;
    for (int kg = 0; kg < HIDC / 4; kg++) {
        float4 a0 = ld4(&st0[kg * 4]);
        float4 a1 = ld4(&st1[kg * 4]);
        float4 a2 = ld4(&st2[kg * 4]);
        float4 a3 = ld4(&st3[kg * 4]);
        const float* pa0 = (const float*)&a0;
        const float* pa1 = (const float*)&a1;
        const float* pa2 = (const float*)&a2;
        const float* pa3 = (const float*)&a3;
        #pragma unroll
        for (int kk = 0; kk < 4; kk++) {
            float4 wr = ld4(&W2[(kg * 4 + kk) * HIDC + lane * 4]);
            acc0.x = fmaf(pa0[kk], wr.x, acc0.x); acc0.y = fmaf(pa0[kk], wr.y, acc0.y);
            acc0.z = fmaf(pa0[kk], wr.z, acc0.z); acc0.w = fmaf(pa0[kk], wr.w, acc0.w);
            acc1.x = fmaf(pa1[kk], wr.x, acc1.x); acc1.y = fmaf(pa1[kk], wr.y, acc1.y);
            acc1.z = fmaf(pa1[kk], wr.z, acc1.z); acc1.w = fmaf(pa1[kk], wr.w, acc1.w);
            acc2.x = fmaf(pa2[kk], wr.x, acc2.x); acc2.y = fmaf(pa2[kk], wr.y, acc2.y);
            acc2.z = fmaf(pa2[kk], wr.z, acc2.z); acc2.w = fmaf(pa2[kk], wr.w, acc2.w);
            acc3.x = fmaf(pa3[kk], wr.x, acc3.x); acc3.y = fmaf(pa3[kk], wr.y, acc3.y);
            acc3.z = fmaf(pa3[kk], wr.z, acc3.z); acc3.w = fmaf(pa3[kk], wr.w, acc3.w);
        }
    }

    int n0 = nb + w * 4;
    st4(&hout[(n0 + 0) * HIDC + lane * 4], elu4(acc0));
    st4(&hout[(n0 + 1) * HIDC + lane * 4], elu4(acc1));
    st4(&hout[(n0 + 2) * HIDC + lane * 4], elu4(acc2));
    st4(&hout[(n0 + 3) * HIDC + lane * 4], elu4(acc3));
}

// ---------------------------------------------------------------------------
// Edge predictor: out[e] = (elu([h[src],h[dst]] @ Wp1 + bp1)) . Wp2 + bp2
// One warp per 4 edges; staged ef in smem (4 x 256 per warp).
// ---------------------------------------------------------------------------
__global__ void edge_pred(const float* __restrict__ h, const int* __restrict__ ei,
                          const float* __restrict__ Wp1, const float* __restrict__ bp1,
                          const float* __restrict__ Wp2, const float* __restrict__ bp2,
                          float* __restrict__ out)
{
    __shared__ float s_f[8 * 4 * 256];  // 32 KB

    int tid  = threadIdx.x;
    int w    = tid >> 5;
    int lane = tid & 31;
    int ebase = blockIdx.x * 32 + w * 4;

    float* sf = &s_f[w * 4 * 256];
    #pragma unroll
    for (int n = 0; n < 4; n++) {
        int e   = ebase + n;
        int src = ei[e];
        int dst = ei[N_EDGESC + e];
        st4(&sf[n * 256 +       lane * 4], ld4(&h[src * HIDC + lane * 4]));
        st4(&sf[n * 256 + 128 + lane * 4], ld4(&h[dst * HIDC + lane * 4]));
    }
    __syncwarp();

    float4 bv = ld4(&bp1[lane * 4]);
    float4 acc0 = bv, acc1 = bv, acc2 = bv, acc3 = bv;
    for (int kg = 0; kg < 64; kg++) {
        float4 a0 = ld4(&sf[0 * 256 + kg * 4]);
        float4 a1 = ld4(&sf[1 * 256 + kg * 4]);
        float4 a2 = ld4(&sf[2 * 256 + kg * 4]);
        float4 a3 = ld4(&sf[3 * 256 + kg * 4]);
        const float* pa0 = (const float*)&a0;
        const float* pa1 = (const float*)&a1;
        const float* pa2 = (const float*)&a2;
        const float* pa3 = (const float*)&a3;
        #pragma unroll
        for (int kk = 0; kk < 4; kk++) {
            float4 wr = ld4(&Wp1[(kg * 4 + kk) * HIDC + lane * 4]);
            acc0.x = fmaf(pa0[kk], wr.x, acc0.x); acc0.y = fmaf(pa0[kk], wr.y, acc0.y);
            acc0.z = fmaf(pa0[kk], wr.z, acc0.z); acc0.w = fmaf(pa0[kk], wr.w, acc0.w);
            acc1.x = fmaf(pa1[kk], wr.x, acc1.x); acc1.y = fmaf(pa1[kk], wr.y, acc1.y);
            acc1.z = fmaf(pa1[kk], wr.z, acc1.z); acc1.w = fmaf(pa1[kk], wr.w, acc1.w);
            acc2.x = fmaf(pa2[kk], wr.x, acc2.x); acc2.y = fmaf(pa2[kk], wr.y, acc2.y);
            acc2.z = fmaf(pa2[kk], wr.z, acc2.z); acc2.w = fmaf(pa2[kk], wr.w, acc2.w);
            acc3.x = fmaf(pa3[kk], wr.x, acc3.x); acc3.y = fmaf(pa3[kk], wr.y, acc3.y);
            acc3.z = fmaf(pa3[kk], wr.z, acc3.z); acc3.w = fmaf(pa3[kk], wr.w, acc3.w);
        }
    }

    float4 w2 = ld4(&Wp2[lane * 4]);
    float bp2v = bp2[0];

    float4 t;
    float p;
    #pragma unroll
    for (int n = 0; n < 4; n++) {
        float4 a = (n == 0) ? acc0 : (n == 1) ? acc1 : (n == 2) ? acc2 : acc3;
        t = elu4(a);
        p = t.x * w2.x + t.y * w2.y + t.z * w2.z + t.w * w2.w;
        #pragma unroll
        for (int off = 16; off; off >>= 1)
            p += __shfl_xor_sync(0xffffffffu, p, off);
        if (lane == 0) out[ebase + n] = p + bp2v;
    }
}

// ---------------------------------------------------------------------------
extern "C" void kernel_launch(void* const* d_in, const int* in_sizes, int n_in,
                              void* d_out, int out_size)
{
    const float* x    = (const float*)d_in[0];
    const int*   ei   = (const int*)  d_in[1];
    const float* ea   = (const float*)d_in[2];
    const float* We0  = (const float*)d_in[3];
    const float* be0  = (const float*)d_in[4];
    const float* W10  = (const float*)d_in[5];
    const float* b10  = (const float*)d_in[6];
    const float* W20  = (const float*)d_in[7];
    const float* b20  = (const float*)d_in[8];
    const float* We_s = (const float*)d_in[9];
    const float* be_s = (const float*)d_in[10];
    const float* W1_s = (const float*)d_in[11];
    const float* b1_s = (const float*)d_in[12];
    const float* W2_s = (const float*)d_in[13];
    const float* b2_s = (const float*)d_in[14];
    const float* Wp1  = (const float*)d_in[15];
    const float* bp1  = (const float*)d_in[16];
    const float* Wp2  = (const float*)d_in[17];
    const float* bp2  = (const float*)d_in[18];
    float* out = (float*)d_out;

    float *hA, *hB, *ag;
    cudaGetSymbolAddress((void**)&hA, g_h);
    cudaGetSymbolAddress((void**)&hB, g_hn);
    cudaGetSymbolAddress((void**)&ag, g_aggr);

    // ---- Layer 0 (NODE_IN=16 -> HID) ----
    cudaMemsetAsync(ag, 0, (size_t)N_NODESC * NODE_INC * sizeof(float));
    edge_layer0<<<(N_EDGESC * 16) / 256, 256>>>(x, ei, ea, We0, be0, ag);
    node_mlp<NODE_INC><<<N_NODESC / 32, 256>>>(x, ag, W10, b10, W20, b20, hA);

    // ---- Layers 1..4 (HID -> HID) ----
    for (int l = 0; l < 4; l++) {
        cudaMemsetAsync(ag, 0, (size_t)N_NODESC * HIDC * sizeof(float));
        edge_msg<<<N_EDGESC / 8, 256>>>(hA, ei, ea,
                                        We_s + l * HIDC, be_s + l * HIDC, ag);
        node_mlp<HIDC><<<N_NODESC / 32, 256>>>(hA, ag,
                                               W1_s + l * HIDC * HIDC, b1_s + l * HIDC,
                                               W2_s + l * HIDC * HIDC, b2_s + l * HIDC, hB);
        float* t = hA; hA = hB; hB = t;
    }

    // ---- Edge predictor ----
    edge_pred<<<N_EDGESC / 32, 256>>>(hA, ei, Wp1, bp1, Wp2, bp2, out);
}

// round 2
// speedup vs baseline: 1.9013x; 1.9013x over previous
#include <cuda_runtime.h>
#include <math.h>

#define N_NODES_ 100000
#define N_EDGES_ 500000
#define HID_ 128
#define NIN_ 16
#define SCAN_B 1024
#define NBLK_ ((N_NODES_ + SCAN_B - 1) / SCAN_B)   // 98

// ---- static scratch (no allocations allowed) ----
__device__ float g_h  [N_NODES_ * HID_];
__device__ float g_hn [N_NODES_ * HID_];
__device__ float g_P  [N_NODES_ * 2 * HID_];   // edge-pred node factors; reused as aggr16
__device__ int   g_deg   [N_NODES_];
__device__ int   g_incl  [N_NODES_];
__device__ int   g_rowptr[N_NODES_ + 1];
__device__ int   g_cursor[N_NODES_];
__device__ int   g_bsum  [NBLK_];
__device__ int   g_boff  [NBLK_];
__device__ int   g_csrc  [N_EDGES_];
__device__ float g_cea   [N_EDGES_];

__device__ __forceinline__ float4 ld4(const float* p) { return *reinterpret_cast<const float4*>(p); }
__device__ __forceinline__ void st4(float* p, float4 v) { *reinterpret_cast<float4*>(p) = v; }
__device__ __forceinline__ float eluf(float x) { return x > 0.f ? x : expm1f(x); }
__device__ __forceinline__ float4 elu4(float4 v) {
    v.x = eluf(v.x); v.y = eluf(v.y); v.z = eluf(v.z); v.w = eluf(v.w); return v;
}

// ---------------------------------------------------------------------------
// CSR build
// ---------------------------------------------------------------------------
__global__ void k_hist(const int* __restrict__ ei) {
    int e = blockIdx.x * blockDim.x + threadIdx.x;
    if (e < N_EDGES_) atomicAdd(&g_deg[ei[N_EDGES_ + e]], 1);
}

__global__ void k_scanA() {
    __shared__ int s[SCAN_B];
    int t = threadIdx.x;
    int g = blockIdx.x * SCAN_B + t;
    int v = (g < N_NODES_) ? g_deg[g] : 0;
    s[t] = v; __syncthreads();
    for (int d = 1; d < SCAN_B; d <<= 1) {
        int u = (t >= d) ? s[t - d] : 0;
        __syncthreads(); s[t] += u; __syncthreads();
    }
    if (g < N_NODES_) g_incl[g] = s[t];
    if (t == SCAN_B - 1) g_bsum[blockIdx.x] = s[t];
}

__global__ void k_scanB() {
    __shared__ int s[128];
    int t = threadIdx.x;
    int v = (t < NBLK_) ? g_bsum[t] : 0;
    s[t] = v; __syncthreads();
    for (int d = 1; d < 128; d <<= 1) {
        int u = (t >= d) ? s[t - d] : 0;
        __syncthreads(); s[t] += u; __syncthreads();
    }
    if (t < NBLK_) g_boff[t] = s[t] - v;     // exclusive
}

__global__ void k_scanC() {
    int g = blockIdx.x * SCAN_B + threadIdx.x;
    if (g >= N_NODES_) return;
    int ex = g_incl[g] - g_deg[g] + g_boff[blockIdx.x];
    g_rowptr[g] = ex;
    g_cursor[g] = ex;
    if (g == N_NODES_ - 1) g_rowptr[N_NODES_] = g_incl[g] + g_boff[blockIdx.x];
}

__global__ void k_fill(const int* __restrict__ ei, const float* __restrict__ ea) {
    int e = blockIdx.x * blockDim.x + threadIdx.x;
    if (e >= N_EDGES_) return;
    int dst = ei[N_EDGES_ + e];
    int slot = atomicAdd(&g_cursor[dst], 1);
    g_csrc[slot] = ei[e];
    g_cea[slot]  = ea[e];
}

// ---------------------------------------------------------------------------
// Layer-0 aggregation (16 features) via CSR gather — no atomics.
// Thread = (node, feat). 2 nodes per warp.
// ---------------------------------------------------------------------------
__global__ void k_aggr0(const float* __restrict__ x, const float* __restrict__ We,
                        const float* __restrict__ be, float* __restrict__ aggr)
{
    int t = blockIdx.x * blockDim.x + threadIdx.x;
    int node = t >> 4;
    int f = t & 15;
    if (node >= N_NODES_) return;
    int beg = g_rowptr[node], end = g_rowptr[node + 1];
    float w = We[f], b = be[f], acc = 0.f;
    for (int p = beg; p < end; p++) {
        float m = x[g_csrc[p] * NIN_ + f] + g_cea[p] * w + b;
        acc += fmaxf(m, 0.f);
    }
    aggr[node * NIN_ + f] = acc;
}

// ---------------------------------------------------------------------------
// Layer-0 node MLP (KIN=16): hout = elu( elu((x+aggr)@W1+b1) @ W2 + b2 )
// ---------------------------------------------------------------------------
__global__ void node_mlp16(const float* __restrict__ xin, const float* __restrict__ aggr,
                           const float* __restrict__ W1, const float* __restrict__ b1,
                           const float* __restrict__ W2, const float* __restrict__ b2,
                           float* __restrict__ hout)
{
    __shared__ float s_in[32 * NIN_];
    __shared__ float s_t [32 * HID_];

    int tid = threadIdx.x;
    int nb  = blockIdx.x * 32;

    for (int i = tid; i < 32 * NIN_; i += 256) {
        int node = i / NIN_, k = i % NIN_;
        int gi = (nb + node) * NIN_ + k;
        s_in[i] = xin[gi] + aggr[gi];
    }
    __syncthreads();

    int w = tid >> 5, lane = tid & 31;
    const float* sin0 = &s_in[(w * 4 + 0) * NIN_];
    const float* sin1 = &s_in[(w * 4 + 1) * NIN_];
    const float* sin2 = &s_in[(w * 4 + 2) * NIN_];
    const float* sin3 = &s_in[(w * 4 + 3) * NIN_];

    float4 bv = ld4(&b1[lane * 4]);
    float4 acc0 = bv, acc1 = bv, acc2 = bv, acc3 = bv;
    for (int kg = 0; kg < NIN_ / 4; kg++) {
        float4 a0 = ld4(&sin0[kg * 4]), a1 = ld4(&sin1[kg * 4]);
        float4 a2 = ld4(&sin2[kg * 4]), a3 = ld4(&sin3[kg * 4]);
        const float *pa0 = (const float*)&a0, *pa1 = (const float*)&a1;
        const float *pa2 = (const float*)&a2, *pa3 = (const float*)&a3;
        #pragma unroll
        for (int kk = 0; kk < 4; kk++) {
            float4 wr = ld4(&W1[(kg * 4 + kk) * HID_ + lane * 4]);
            acc0.x = fmaf(pa0[kk], wr.x, acc0.x); acc0.y = fmaf(pa0[kk], wr.y, acc0.y);
            acc0.z = fmaf(pa0[kk], wr.z, acc0.z); acc0.w = fmaf(pa0[kk], wr.w, acc0.w);
            acc1.x = fmaf(pa1[kk], wr.x, acc1.x); acc1.y = fmaf(pa1[kk], wr.y, acc1.y);
            acc1.z = fmaf(pa1[kk], wr.z, acc1.z); acc1.w = fmaf(pa1[kk], wr.w, acc1.w);
            acc2.x = fmaf(pa2[kk], wr.x, acc2.x); acc2.y = fmaf(pa2[kk], wr.y, acc2.y);
            acc2.z = fmaf(pa2[kk], wr.z, acc2.z); acc2.w = fmaf(pa2[kk], wr.w, acc2.w);
            acc3.x = fmaf(pa3[kk], wr.x, acc3.x); acc3.y = fmaf(pa3[kk], wr.y, acc3.y);
            acc3.z = fmaf(pa3[kk], wr.z, acc3.z); acc3.w = fmaf(pa3[kk], wr.w, acc3.w);
        }
    }

    float* st0 = &s_t[(w * 4 + 0) * HID_];
    float* st1 = &s_t[(w * 4 + 1) * HID_];
    float* st2 = &s_t[(w * 4 + 2) * HID_];
    float* st3 = &s_t[(w * 4 + 3) * HID_];
    st4(&st0[lane * 4], elu4(acc0)); st4(&st1[lane * 4], elu4(acc1));
    st4(&st2[lane * 4], elu4(acc2)); st4(&st3[lane * 4], elu4(acc3));
    __syncwarp();

    float4 bv2 = ld4(&b2[lane * 4]);
    acc0 = bv2; acc1 = bv2; acc2 = bv2; acc3 = bv2;
    for (int kg = 0; kg < HID_ / 4; kg++) {
        float4 a0 = ld4(&st0[kg * 4]), a1 = ld4(&st1[kg * 4]);
        float4 a2 = ld4(&st2[kg * 4]), a3 = ld4(&st3[kg * 4]);
        const float *pa0 = (const float*)&a0, *pa1 = (const float*)&a1;
        const float *pa2 = (const float*)&a2, *pa3 = (const float*)&a3;
        #pragma unroll
        for (int kk = 0; kk < 4; kk++) {
            float4 wr = ld4(&W2[(kg * 4 + kk) * HID_ + lane * 4]);
            acc0.x = fmaf(pa0[kk], wr.x, acc0.x); acc0.y = fmaf(pa0[kk], wr.y, acc0.y);
            acc0.z = fmaf(pa0[kk], wr.z, acc0.z); acc0.w = fmaf(pa0[kk], wr.w, acc0.w);
            acc1.x = fmaf(pa1[kk], wr.x, acc1.x); acc1.y = fmaf(pa1[kk], wr.y, acc1.y);
            acc1.z = fmaf(pa1[kk], wr.z, acc1.z); acc1.w = fmaf(pa1[kk], wr.w, acc1.w);
            acc2.x = fmaf(pa2[kk], wr.x, acc2.x); acc2.y = fmaf(pa2[kk], wr.y, acc2.y);
            acc2.z = fmaf(pa2[kk], wr.z, acc2.z); acc2.w = fmaf(pa2[kk], wr.w, acc2.w);
            acc3.x = fmaf(pa3[kk], wr.x, acc3.x); acc3.y = fmaf(pa3[kk], wr.y, acc3.y);
            acc3.z = fmaf(pa3[kk], wr.z, acc3.z); acc3.w = fmaf(pa3[kk], wr.w, acc3.w);
        }
    }

    int n0 = nb + w * 4;
    st4(&hout[(n0 + 0) * HID_ + lane * 4], elu4(acc0));
    st4(&hout[(n0 + 1) * HID_ + lane * 4], elu4(acc1));
    st4(&hout[(n0 + 2) * HID_ + lane * 4], elu4(acc2));
    st4(&hout[(n0 + 3) * HID_ + lane * 4], elu4(acc3));
}

// ---------------------------------------------------------------------------
// Fused GINE layer (HID -> HID): gather aggregation via CSR + node MLP.
// s_in[node] = h[node] + sum_e relu(h[csr_src] + ea*We + be), then MLP.
// Block = 256 threads / 8 warps; warp owns 4 nodes; lane owns 4 output cols.
// ---------------------------------------------------------------------------
__global__ void gine_layer(const float* __restrict__ h,
                           const float* __restrict__ We, const float* __restrict__ be,
                           const float* __restrict__ W1, const float* __restrict__ b1,
                           const float* __restrict__ W2, const float* __restrict__ b2,
                           float* __restrict__ hout)
{
    __shared__ float s_in[32 * HID_];
    __shared__ float s_t [32 * HID_];

    int tid = threadIdx.x;
    int nb  = blockIdx.x * 32;
    int w = tid >> 5, lane = tid & 31;

    // gather prologue (warp-private rows -> __syncwarp is enough)
    {
        float4 wv = ld4(&We[lane * 4]);
        float4 bg = ld4(&be[lane * 4]);
        #pragma unroll
        for (int n = 0; n < 4; n++) {
            int node = nb + w * 4 + n;
            float4 acc = ld4(&h[node * HID_ + lane * 4]);
            int beg = g_rowptr[node], end = g_rowptr[node + 1];
            for (int p = beg; p < end; p++) {
                int s = g_csrc[p];
                float we = g_cea[p];
                float4 hv = ld4(&h[s * HID_ + lane * 4]);
                acc.x += fmaxf(fmaf(we, wv.x, hv.x) + bg.x, 0.f);
                acc.y += fmaxf(fmaf(we, wv.y, hv.y) + bg.y, 0.f);
                acc.z += fmaxf(fmaf(we, wv.z, hv.z) + bg.z, 0.f);
                acc.w += fmaxf(fmaf(we, wv.w, hv.w) + bg.w, 0.f);
            }
            st4(&s_in[(w * 4 + n) * HID_ + lane * 4], acc);
        }
    }
    __syncwarp();

    const float* sin0 = &s_in[(w * 4 + 0) * HID_];
    const float* sin1 = &s_in[(w * 4 + 1) * HID_];
    const float* sin2 = &s_in[(w * 4 + 2) * HID_];
    const float* sin3 = &s_in[(w * 4 + 3) * HID_];

    float4 bv = ld4(&b1[lane * 4]);
    float4 acc0 = bv, acc1 = bv, acc2 = bv, acc3 = bv;
    for (int kg = 0; kg < HID_ / 4; kg++) {
        float4 a0 = ld4(&sin0[kg * 4]), a1 = ld4(&sin1[kg * 4]);
        float4 a2 = ld4(&sin2[kg * 4]), a3 = ld4(&sin3[kg * 4]);
        const float *pa0 = (const float*)&a0, *pa1 = (const float*)&a1;
        const float *pa2 = (const float*)&a2, *pa3 = (const float*)&a3;
        #pragma unroll
        for (int kk = 0; kk < 4; kk++) {
            float4 wr = ld4(&W1[(kg * 4 + kk) * HID_ + lane * 4]);
            acc0.x = fmaf(pa0[kk], wr.x, acc0.x); acc0.y = fmaf(pa0[kk], wr.y, acc0.y);
            acc0.z = fmaf(pa0[kk], wr.z, acc0.z); acc0.w = fmaf(pa0[kk], wr.w, acc0.w);
            acc1.x = fmaf(pa1[kk], wr.x, acc1.x); acc1.y = fmaf(pa1[kk], wr.y, acc1.y);
            acc1.z = fmaf(pa1[kk], wr.z, acc1.z); acc1.w = fmaf(pa1[kk], wr.w, acc1.w);
            acc2.x = fmaf(pa2[kk], wr.x, acc2.x); acc2.y = fmaf(pa2[kk], wr.y, acc2.y);
            acc2.z = fmaf(pa2[kk], wr.z, acc2.z); acc2.w = fmaf(pa2[kk], wr.w, acc2.w);
            acc3.x = fmaf(pa3[kk], wr.x, acc3.x); acc3.y = fmaf(pa3[kk], wr.y, acc3.y);
            acc3.z = fmaf(pa3[kk], wr.z, acc3.z); acc3.w = fmaf(pa3[kk], wr.w, acc3.w);
        }
    }

    float* st0 = &s_t[(w * 4 + 0) * HID_];
    float* st1 = &s_t[(w * 4 + 1) * HID_];
    float* st2 = &s_t[(w * 4 + 2) * HID_];
    float* st3 = &s_t[(w * 4 + 3) * HID_];
    st4(&st0[lane * 4], elu4(acc0)); st4(&st1[lane * 4], elu4(acc1));
    st4(&st2[lane * 4], elu4(acc2)); st4(&st3[lane * 4], elu4(acc3));
    __syncwarp();

    float4 bv2 = ld4(&b2[lane * 4]);
    acc0 = bv2; acc1 = bv2; acc2 = bv2; acc3 = bv2;
    for (int kg = 0; kg < HID_ / 4; kg++) {
        float4 a0 = ld4(&st0[kg * 4]), a1 = ld4(&st1[kg * 4]);
        float4 a2 = ld4(&st2[kg * 4]), a3 = ld4(&st3[kg * 4]);
        const float *pa0 = (const float*)&a0, *pa1 = (const float*)&a1;
        const float *pa2 = (const float*)&a2, *pa3 = (const float*)&a3;
        #pragma unroll
        for (int kk = 0; kk < 4; kk++) {
            float4 wr = ld4(&W2[(kg * 4 + kk) * HID_ + lane * 4]);
            acc0.x = fmaf(pa0[kk], wr.x, acc0.x); acc0.y = fmaf(pa0[kk], wr.y, acc0.y);
            acc0.z = fmaf(pa0[kk], wr.z, acc0.z); acc0.w = fmaf(pa0[kk], wr.w, acc0.w);
            acc1.x = fmaf(pa1[kk], wr.x, acc1.x); acc1.y = fmaf(pa1[kk], wr.y, acc1.y);
            acc1.z = fmaf(pa1[kk], wr.z, acc1.z); acc1.w = fmaf(pa1[kk], wr.w, acc1.w);
            acc2.x = fmaf(pa2[kk], wr.x, acc2.x); acc2.y = fmaf(pa2[kk], wr.y, acc2.y);
            acc2.z = fmaf(pa2[kk], wr.z, acc2.z); acc2.w = fmaf(pa2[kk], wr.w, acc2.w);
            acc3.x = fmaf(pa3[kk], wr.x, acc3.x); acc3.y = fmaf(pa3[kk], wr.y, acc3.y);
            acc3.z = fmaf(pa3[kk], wr.z, acc3.z); acc3.w = fmaf(pa3[kk], wr.w, acc3.w);
        }
    }

    int n0 = nb + w * 4;
    st4(&hout[(n0 + 0) * HID_ + lane * 4], elu4(acc0));
    st4(&hout[(n0 + 1) * HID_ + lane * 4], elu4(acc1));
    st4(&hout[(n0 + 2) * HID_ + lane * 4], elu4(acc2));
    st4(&hout[(n0 + 3) * HID_ + lane * 4], elu4(acc3));
}

// ---------------------------------------------------------------------------
// Edge-predictor node factors: P[i, 0:128] = h[i]@Wp1[0:128,:],
//                              P[i,128:256] = h[i]@Wp1[128:256,:]
// ---------------------------------------------------------------------------
__global__ void k_prednode(const float* __restrict__ h, const float* __restrict__ Wp1,
                           float* __restrict__ P)
{
    __shared__ float s_in[32 * HID_];

    int tid = threadIdx.x;
    int nb  = blockIdx.x * 32;

    for (int i = tid; i < 32 * HID_; i += 256)
        s_in[i] = h[nb * HID_ + i];
    __syncthreads();

    int w = tid >> 5, lane = tid & 31;
    const float* sin0 = &s_in[(w * 4 + 0) * HID_];
    const float* sin1 = &s_in[(w * 4 + 1) * HID_];
    const float* sin2 = &s_in[(w * 4 + 2) * HID_];
    const float* sin3 = &s_in[(w * 4 + 3) * HID_];

    float4 A0 = {0,0,0,0}, A1 = A0, A2 = A0, A3 = A0;
    float4 B0 = A0, B1 = A0, B2 = A0, B3 = A0;

    for (int kg = 0; kg < HID_ / 4; kg++) {
        float4 a0 = ld4(&sin0[kg * 4]), a1 = ld4(&sin1[kg * 4]);
        float4 a2 = ld4(&sin2[kg * 4]), a3 = ld4(&sin3[kg * 4]);
        const float *pa0 = (const float*)&a0, *pa1 = (const float*)&a1;
        const float *pa2 = (const float*)&a2, *pa3 = (const float*)&a3;
        #pragma unroll
        for (int kk = 0; kk < 4; kk++) {
            int k = kg * 4 + kk;
            float4 wa = ld4(&Wp1[k * HID_ + lane * 4]);
            float4 wb = ld4(&Wp1[(HID_ + k) * HID_ + lane * 4]);
            A0.x = fmaf(pa0[kk], wa.x, A0.x); A0.y = fmaf(pa0[kk], wa.y, A0.y);
            A0.z = fmaf(pa0[kk], wa.z, A0.z); A0.w = fmaf(pa0[kk], wa.w, A0.w);
            A1.x = fmaf(pa1[kk], wa.x, A1.x); A1.y = fmaf(pa1[kk], wa.y, A1.y);
            A1.z = fmaf(pa1[kk], wa.z, A1.z); A1.w = fmaf(pa1[kk], wa.w, A1.w);
            A2.x = fmaf(pa2[kk], wa.x, A2.x); A2.y = fmaf(pa2[kk], wa.y, A2.y);
            A2.z = fmaf(pa2[kk], wa.z, A2.z); A2.w = fmaf(pa2[kk], wa.w, A2.w);
            A3.x = fmaf(pa3[kk], wa.x, A3.x); A3.y = fmaf(pa3[kk], wa.y, A3.y);
            A3.z = fmaf(pa3[kk], wa.z, A3.z); A3.w = fmaf(pa3[kk], wa.w, A3.w);
            B0.x = fmaf(pa0[kk], wb.x, B0.x); B0.y = fmaf(pa0[kk], wb.y, B0.y);
            B0.z = fmaf(pa0[kk], wb.z, B0.z); B0.w = fmaf(pa0[kk], wb.w, B0.w);
            B1.x = fmaf(pa1[kk], wb.x, B1.x); B1.y = fmaf(pa1[kk], wb.y, B1.y);
            B1.z = fmaf(pa1[kk], wb.z, B1.z); B1.w = fmaf(pa1[kk], wb.w, B1.w);
            B2.x = fmaf(pa2[kk], wb.x, B2.x); B2.y = fmaf(pa2[kk], wb.y, B2.y);
            B2.z = fmaf(pa2[kk], wb.z, B2.z); B2.w = fmaf(pa2[kk], wb.w, B2.w);
            B3.x = fmaf(pa3[kk], wb.x, B3.x); B3.y = fmaf(pa3[kk], wb.y, B3.y);
            B3.z = fmaf(pa3[kk], wb.z, B3.z); B3.w = fmaf(pa3[kk], wb.w, B3.w);
        }
    }

    int n0 = nb + w * 4;
    st4(&P[(n0 + 0) * 256 + lane * 4], A0);        st4(&P[(n0 + 0) * 256 + 128 + lane * 4], B0);
    st4(&P[(n0 + 1) * 256 + lane * 4], A1);        st4(&P[(n0 + 1) * 256 + 128 + lane * 4], B1);
    st4(&P[(n0 + 2) * 256 + lane * 4], A2);        st4(&P[(n0 + 2) * 256 + 128 + lane * 4], B2);
    st4(&P[(n0 + 3) * 256 + lane * 4], A3);        st4(&P[(n0 + 3) * 256 + 128 + lane * 4], B3);
}

// ---------------------------------------------------------------------------
// Per-edge predictor epilogue: out[e] = elu(A[src]+B[dst]+bp1) . Wp2 + bp2
// One warp handles 4 edges.
// ---------------------------------------------------------------------------
__global__ void k_prededge(const float* __restrict__ P, const int* __restrict__ ei,
                           const float* __restrict__ bp1, const float* __restrict__ Wp2,
                           const float* __restrict__ bp2, float* __restrict__ out)
{
    int warp = (blockIdx.x * blockDim.x + threadIdx.x) >> 5;
    int lane = threadIdx.x & 31;
    int e0 = warp * 4;
    if (e0 >= N_EDGES_) return;

    float4 bv = ld4(&bp1[lane * 4]);
    float4 w2 = ld4(&Wp2[lane * 4]);
    float c = bp2[0];

    #pragma unroll
    for (int n = 0; n < 4; n++) {
        int e = e0 + n;
        int src = ei[e];
        int dst = ei[N_EDGES_ + e];
        float4 a = ld4(&P[src * 256 + lane * 4]);
        float4 b = ld4(&P[dst * 256 + 128 + lane * 4]);
        float4 t;
        t.x = eluf(a.x + b.x + bv.x);
        t.y = eluf(a.y + b.y + bv.y);
        t.z = eluf(a.z + b.z + bv.z);
        t.w = eluf(a.w + b.w + bv.w);
        float p = t.x * w2.x + t.y * w2.y + t.z * w2.z + t.w * w2.w;
        #pragma unroll
        for (int off = 16; off; off >>= 1)
            p += __shfl_xor_sync(0xffffffffu, p, off);
        if (lane == 0) out[e] = p + c;
    }
}

// ---------------------------------------------------------------------------
extern "C" void kernel_launch(void* const* d_in, const int* in_sizes, int n_in,
                              void* d_out, int out_size)
{
    const float* x    = (const float*)d_in[0];
    const int*   ei   = (const int*)  d_in[1];
    const float* ea   = (const float*)d_in[2];
    const float* We0  = (const float*)d_in[3];
    const float* be0  = (const float*)d_in[4];
    const float* W10  = (const float*)d_in[5];
    const float* b10  = (const float*)d_in[6];
    const float* W20  = (const float*)d_in[7];
    const float* b20  = (const float*)d_in[8];
    const float* We_s = (const float*)d_in[9];
    const float* be_s = (const float*)d_in[10];
    const float* W1_s = (const float*)d_in[11];
    const float* b1_s = (const float*)d_in[12];
    const float* W2_s = (const float*)d_in[13];
    const float* b2_s = (const float*)d_in[14];
    const float* Wp1  = (const float*)d_in[15];
    const float* bp1  = (const float*)d_in[16];
    const float* Wp2  = (const float*)d_in[17];
    const float* bp2  = (const float*)d_in[18];
    float* out = (float*)d_out;

    float *hA, *hB, *P;
    int *deg;
    cudaGetSymbolAddress((void**)&hA, g_h);
    cudaGetSymbolAddress((void**)&hB, g_hn);
    cudaGetSymbolAddress((void**)&P,  g_P);
    cudaGetSymbolAddress((void**)&deg, g_deg);

    // ---- CSR build ----
    cudaMemsetAsync(deg, 0, N_NODES_ * sizeof(int));
    k_hist <<<(N_EDGES_ + 255) / 256, 256>>>(ei);
    k_scanA<<<NBLK_, SCAN_B>>>();
    k_scanB<<<1, 128>>>();
    k_scanC<<<NBLK_, SCAN_B>>>();
    k_fill <<<(N_EDGES_ + 255) / 256, 256>>>(ei, ea);

    // ---- Layer 0 (16 -> 128): CSR gather + MLP ----
    k_aggr0<<<(N_NODES_ * 16 + 255) / 256, 256>>>(x, We0, be0, P);   // reuse P as aggr16
    node_mlp16<<<N_NODES_ / 32, 256>>>(x, P, W10, b10, W20, b20, hA);

    // ---- Layers 1..4 (fused gather + MLP) ----
    for (int l = 0; l < 4; l++) {
        gine_layer<<<N_NODES_ / 32, 256>>>(hA,
                                           We_s + l * HID_, be_s + l * HID_,
                                           W1_s + l * HID_ * HID_, b1_s + l * HID_,
                                           W2_s + l * HID_ * HID_, b2_s + l * HID_, hB);
        float* t = hA; hA = hB; hB = t;
    }

    // ---- Edge predictor: node-level factorization + per-edge epilogue ----
    k_prednode<<<N_NODES_ / 32, 256>>>(hA, Wp1, P);
    k_prededge<<<(N_EDGES_ / 4 * 32 + 255) / 256, 256>>>(P, ei, bp1, Wp2, bp2, out);
}

// round 3
// speedup vs baseline: 2.0529x; 1.0797x over previous
#include <cuda_runtime.h>
#include <math.h>

#define N_NODES_ 100000
#define N_EDGES_ 500000
#define HID_ 128
#define NIN_ 16
#define SCAN_B 1024
#define NBLK_ ((N_NODES_ + SCAN_B - 1) / SCAN_B)   // 98

// ---- static scratch (no allocations allowed) ----
__device__ float g_h  [N_NODES_ * HID_];
__device__ float g_hn [N_NODES_ * HID_];
__device__ float g_P  [N_NODES_ * 2 * HID_];   // edge-pred node factors; reused as aggr16
__device__ int   g_deg   [N_NODES_];
__device__ int   g_incl  [N_NODES_];
__device__ int   g_rowptr[N_NODES_ + 1];
__device__ int   g_cursor[N_NODES_];
__device__ int   g_bsum  [NBLK_];
__device__ int   g_boff  [NBLK_];
__device__ int   g_csrc  [N_EDGES_];
__device__ float g_cea   [N_EDGES_];

__device__ __forceinline__ float4 ld4(const float* p) { return *reinterpret_cast<const float4*>(p); }
__device__ __forceinline__ void st4(float* p, float4 v) { *reinterpret_cast<float4*>(p) = v; }
__device__ __forceinline__ float eluf(float x) { return x > 0.f ? x : expm1f(x); }
__device__ __forceinline__ float4 elu4(float4 v) {
    v.x = eluf(v.x); v.y = eluf(v.y); v.z = eluf(v.z); v.w = eluf(v.w); return v;
}

// ---- packed fp32 (f32x2) helpers: exact fp32 math, 2 lanes per instruction ----
__device__ __forceinline__ unsigned long long pkdup(float a) {
    unsigned long long r;
    asm("mov.b64 %0, {%1, %1};" : "=l"(r) : "f"(a));
    return r;
}
__device__ __forceinline__ void fma2(unsigned long long& d, unsigned long long a, unsigned long long b) {
    asm("fma.rn.f32x2 %0, %1, %2, %3;" : "=l"(d) : "l"(a), "l"(b), "l"(d));
}
__device__ __forceinline__ float2 upk(unsigned long long v) {
    float2 f;
    asm("mov.b64 {%0, %1}, %2;" : "=f"(f.x), "=f"(f.y) : "l"(v));
    return f;
}
__device__ __forceinline__ float4 acc2f4(unsigned long long lo, unsigned long long hi) {
    float2 l = upk(lo), h = upk(hi);
    return make_float4(l.x, l.y, h.x, h.y);
}

// ---------------------------------------------------------------------------
// GEMV core: 4 rows (s0..s3, length KIN) x W[KIN, HID_], lane owns cols
// lane*4..lane*4+3. Accumulators are packed f32x2 pairs.
// ---------------------------------------------------------------------------
template <int KIN>
__device__ __forceinline__ void gemv4(const float* s0, const float* s1,
                                      const float* s2, const float* s3,
                                      const float* __restrict__ W,
                                      const float* __restrict__ b,
                                      int lane, float4 out[4])
{
    ulonglong2 bv = *reinterpret_cast<const ulonglong2*>(&b[lane * 4]);
    unsigned long long aL0 = bv.x, aH0 = bv.y;
    unsigned long long aL1 = bv.x, aH1 = bv.y;
    unsigned long long aL2 = bv.x, aH2 = bv.y;
    unsigned long long aL3 = bv.x, aH3 = bv.y;

    #pragma unroll 4
    for (int kg = 0; kg < KIN / 4; kg++) {
        float4 a0 = ld4(&s0[kg * 4]);
        float4 a1 = ld4(&s1[kg * 4]);
        float4 a2 = ld4(&s2[kg * 4]);
        float4 a3 = ld4(&s3[kg * 4]);
        const float* p0 = (const float*)&a0;
        const float* p1 = (const float*)&a1;
        const float* p2 = (const float*)&a2;
        const float* p3 = (const float*)&a3;
        #pragma unroll
        for (int kk = 0; kk < 4; kk++) {
            ulonglong2 wv = *reinterpret_cast<const ulonglong2*>(&W[(kg * 4 + kk) * HID_ + lane * 4]);
            unsigned long long d0 = pkdup(p0[kk]);
            unsigned long long d1 = pkdup(p1[kk]);
            unsigned long long d2 = pkdup(p2[kk]);
            unsigned long long d3 = pkdup(p3[kk]);
            fma2(aL0, d0, wv.x); fma2(aH0, d0, wv.y);
            fma2(aL1, d1, wv.x); fma2(aH1, d1, wv.y);
            fma2(aL2, d2, wv.x); fma2(aH2, d2, wv.y);
            fma2(aL3, d3, wv.x); fma2(aH3, d3, wv.y);
        }
    }
    out[0] = acc2f4(aL0, aH0);
    out[1] = acc2f4(aL1, aH1);
    out[2] = acc2f4(aL2, aH2);
    out[3] = acc2f4(aL3, aH3);
}

// ---------------------------------------------------------------------------
// CSR build
// ---------------------------------------------------------------------------
__global__ void k_hist(const int* __restrict__ ei) {
    int e = blockIdx.x * blockDim.x + threadIdx.x;
    if (e < N_EDGES_) atomicAdd(&g_deg[ei[N_EDGES_ + e]], 1);
}

__global__ void k_scanA() {
    __shared__ int s[SCAN_B];
    int t = threadIdx.x;
    int g = blockIdx.x * SCAN_B + t;
    int v = (g < N_NODES_) ? g_deg[g] : 0;
    s[t] = v; __syncthreads();
    for (int d = 1; d < SCAN_B; d <<= 1) {
        int u = (t >= d) ? s[t - d] : 0;
        __syncthreads(); s[t] += u; __syncthreads();
    }
    if (g < N_NODES_) g_incl[g] = s[t];
    if (t == SCAN_B - 1) g_bsum[blockIdx.x] = s[t];
}

__global__ void k_scanB() {
    __shared__ int s[128];
    int t = threadIdx.x;
    int v = (t < NBLK_) ? g_bsum[t] : 0;
    s[t] = v; __syncthreads();
    for (int d = 1; d < 128; d <<= 1) {
        int u = (t >= d) ? s[t - d] : 0;
        __syncthreads(); s[t] += u; __syncthreads();
    }
    if (t < NBLK_) g_boff[t] = s[t] - v;     // exclusive
}

__global__ void k_scanC() {
    int g = blockIdx.x * SCAN_B + threadIdx.x;
    if (g >= N_NODES_) return;
    int ex = g_incl[g] - g_deg[g] + g_boff[blockIdx.x];
    g_rowptr[g] = ex;
    g_cursor[g] = ex;
    if (g == N_NODES_ - 1) g_rowptr[N_NODES_] = g_incl[g] + g_boff[blockIdx.x];
}

__global__ void k_fill(const int* __restrict__ ei, const float* __restrict__ ea) {
    int e = blockIdx.x * blockDim.x + threadIdx.x;
    if (e >= N_EDGES_) return;
    int dst = ei[N_EDGES_ + e];
    int slot = atomicAdd(&g_cursor[dst], 1);
    g_csrc[slot] = ei[e];
    g_cea[slot]  = ea[e];
}

// ---------------------------------------------------------------------------
// Layer-0 aggregation (16 features) via CSR gather — no atomics.
// ---------------------------------------------------------------------------
__global__ void k_aggr0(const float* __restrict__ x, const float* __restrict__ We,
                        const float* __restrict__ be, float* __restrict__ aggr)
{
    int t = blockIdx.x * blockDim.x + threadIdx.x;
    int node = t >> 4;
    int f = t & 15;
    if (node >= N_NODES_) return;
    int beg = g_rowptr[node], end = g_rowptr[node + 1];
    float w = We[f], b = be[f], acc = 0.f;
    for (int p = beg; p < end; p++) {
        float m = x[g_csrc[p] * NIN_ + f] + g_cea[p] * w + b;
        acc += fmaxf(m, 0.f);
    }
    aggr[node * NIN_ + f] = acc;
}

// ---------------------------------------------------------------------------
// Layer-0 node MLP (KIN=16)
// ---------------------------------------------------------------------------
__global__ void node_mlp16(const float* __restrict__ xin, const float* __restrict__ aggr,
                           const float* __restrict__ W1, const float* __restrict__ b1,
                           const float* __restrict__ W2, const float* __restrict__ b2,
                           float* __restrict__ hout)
{
    __shared__ float s_in[32 * NIN_];
    __shared__ float s_t [32 * HID_];

    int tid = threadIdx.x;
    int nb  = blockIdx.x * 32;

    for (int i = tid; i < 32 * NIN_; i += 256) {
        int node = i / NIN_, k = i % NIN_;
        int gi = (nb + node) * NIN_ + k;
        s_in[i] = xin[gi] + aggr[gi];
    }
    __syncthreads();

    int w = tid >> 5, lane = tid & 31;
    float4 o[4];
    gemv4<NIN_>(&s_in[(w * 4 + 0) * NIN_], &s_in[(w * 4 + 1) * NIN_],
                &s_in[(w * 4 + 2) * NIN_], &s_in[(w * 4 + 3) * NIN_],
                W1, b1, lane, o);

    float* st0 = &s_t[(w * 4 + 0) * HID_];
    float* st1 = &s_t[(w * 4 + 1) * HID_];
    float* st2 = &s_t[(w * 4 + 2) * HID_];
    float* st3 = &s_t[(w * 4 + 3) * HID_];
    st4(&st0[lane * 4], elu4(o[0])); st4(&st1[lane * 4], elu4(o[1]));
    st4(&st2[lane * 4], elu4(o[2])); st4(&st3[lane * 4], elu4(o[3]));
    __syncwarp();

    gemv4<HID_>(st0, st1, st2, st3, W2, b2, lane, o);

    int n0 = nb + w * 4;
    st4(&hout[(n0 + 0) * HID_ + lane * 4], elu4(o[0]));
    st4(&hout[(n0 + 1) * HID_ + lane * 4], elu4(o[1]));
    st4(&hout[(n0 + 2) * HID_ + lane * 4], elu4(o[2]));
    st4(&hout[(n0 + 3) * HID_ + lane * 4], elu4(o[3]));
}

// ---------------------------------------------------------------------------
// Fused GINE layer (HID -> HID): CSR gather + MLP, packed-fp32 GEMV.
// ---------------------------------------------------------------------------
__global__ void gine_layer(const float* __restrict__ h,
                           const float* __restrict__ We, const float* __restrict__ be,
                           const float* __restrict__ W1, const float* __restrict__ b1,
                           const float* __restrict__ W2, const float* __restrict__ b2,
                           float* __restrict__ hout)
{
    __shared__ float s_in[32 * HID_];
    __shared__ float s_t [32 * HID_];

    int tid = threadIdx.x;
    int nb  = blockIdx.x * 32;
    int w = tid >> 5, lane = tid & 31;

    // gather prologue (warp-private rows)
    {
        float4 wv = ld4(&We[lane * 4]);
        float4 bg = ld4(&be[lane * 4]);
        #pragma unroll
        for (int n = 0; n < 4; n++) {
            int node = nb + w * 4 + n;
            float4 acc = ld4(&h[node * HID_ + lane * 4]);
            int beg = g_rowptr[node], end = g_rowptr[node + 1];
            for (int p = beg; p < end; p++) {
                int s = g_csrc[p];
                float we = g_cea[p];
                float4 hv = ld4(&h[s * HID_ + lane * 4]);
                acc.x += fmaxf(fmaf(we, wv.x, hv.x) + bg.x, 0.f);
                acc.y += fmaxf(fmaf(we, wv.y, hv.y) + bg.y, 0.f);
                acc.z += fmaxf(fmaf(we, wv.z, hv.z) + bg.z, 0.f);
                acc.w += fmaxf(fmaf(we, wv.w, hv.w) + bg.w, 0.f);
            }
            st4(&s_in[(w * 4 + n) * HID_ + lane * 4], acc);
        }
    }
    __syncwarp();

    float4 o[4];
    float* si0 = &s_in[(w * 4 + 0) * HID_];
    float* si1 = &s_in[(w * 4 + 1) * HID_];
    float* si2 = &s_in[(w * 4 + 2) * HID_];
    float* si3 = &s_in[(w * 4 + 3) * HID_];
    gemv4<HID_>(si0, si1, si2, si3, W1, b1, lane, o);

    float* st0 = &s_t[(w * 4 + 0) * HID_];
    float* st1 = &s_t[(w * 4 + 1) * HID_];
    float* st2 = &s_t[(w * 4 + 2) * HID_];
    float* st3 = &s_t[(w * 4 + 3) * HID_];
    st4(&st0[lane * 4], elu4(o[0])); st4(&st1[lane * 4], elu4(o[1]));
    st4(&st2[lane * 4], elu4(o[2])); st4(&st3[lane * 4], elu4(o[3]));
    __syncwarp();

    gemv4<HID_>(st0, st1, st2, st3, W2, b2, lane, o);

    int n0 = nb + w * 4;
    st4(&hout[(n0 + 0) * HID_ + lane * 4], elu4(o[0]));
    st4(&hout[(n0 + 1) * HID_ + lane * 4], elu4(o[1]));
    st4(&hout[(n0 + 2) * HID_ + lane * 4], elu4(o[2]));
    st4(&hout[(n0 + 3) * HID_ + lane * 4], elu4(o[3]));
}

// ---------------------------------------------------------------------------
// Edge-predictor node factors (fused A/B weight halves, packs reused):
// P[i, 0:128] = h[i]@Wp1[0:128,:],  P[i,128:256] = h[i]@Wp1[128:256,:]
// ---------------------------------------------------------------------------
__global__ void k_prednode(const float* __restrict__ h, const float* __restrict__ Wp1,
                           float* __restrict__ P)
{
    __shared__ float s_in[32 * HID_];

    int tid = threadIdx.x;
    int nb  = blockIdx.x * 32;

    for (int i = tid; i < 32 * HID_; i += 256)
        s_in[i] = h[nb * HID_ + i];
    __syncthreads();

    int w = tid >> 5, lane = tid & 31;
    const float* s0 = &s_in[(w * 4 + 0) * HID_];
    const float* s1 = &s_in[(w * 4 + 1) * HID_];
    const float* s2 = &s_in[(w * 4 + 2) * HID_];
    const float* s3 = &s_in[(w * 4 + 3) * HID_];

    unsigned long long AL0 = 0, AH0 = 0, AL1 = 0, AH1 = 0, AL2 = 0, AH2 = 0, AL3 = 0, AH3 = 0;
    unsigned long long BL0 = 0, BH0 = 0, BL1 = 0, BH1 = 0, BL2 = 0, BH2 = 0, BL3 = 0, BH3 = 0;

    #pragma unroll 2
    for (int kg = 0; kg < HID_ / 4; kg++) {
        float4 a0 = ld4(&s0[kg * 4]);
        float4 a1 = ld4(&s1[kg * 4]);
        float4 a2 = ld4(&s2[kg * 4]);
        float4 a3 = ld4(&s3[kg * 4]);
        const float* p0 = (const float*)&a0;
        const float* p1 = (const float*)&a1;
        const float* p2 = (const float*)&a2;
        const float* p3 = (const float*)&a3;
        #pragma unroll
        for (int kk = 0; kk < 4; kk++) {
            int k = kg * 4 + kk;
            ulonglong2 wa = *reinterpret_cast<const ulonglong2*>(&Wp1[k * HID_ + lane * 4]);
            ulonglong2 wb = *reinterpret_cast<const ulonglong2*>(&Wp1[(HID_ + k) * HID_ + lane * 4]);
            unsigned long long d0 = pkdup(p0[kk]);
            unsigned long long d1 = pkdup(p1[kk]);
            unsigned long long d2 = pkdup(p2[kk]);
            unsigned long long d3 = pkdup(p3[kk]);
            fma2(AL0, d0, wa.x); fma2(AH0, d0, wa.y);
            fma2(AL1, d1, wa.x); fma2(AH1, d1, wa.y);
            fma2(AL2, d2, wa.x); fma2(AH2, d2, wa.y);
            fma2(AL3, d3, wa.x); fma2(AH3, d3, wa.y);
            fma2(BL0, d0, wb.x); fma2(BH0, d0, wb.y);
            fma2(BL1, d1, wb.x); fma2(BH1, d1, wb.y);
            fma2(BL2, d2, wb.x); fma2(BH2, d2, wb.y);
            fma2(BL3, d3, wb.x); fma2(BH3, d3, wb.y);
        }
    }

    int n0 = nb + w * 4;
    st4(&P[(n0 + 0) * 256 + lane * 4], acc2f4(AL0, AH0));
    st4(&P[(n0 + 1) * 256 + lane * 4], acc2f4(AL1, AH1));
    st4(&P[(n0 + 2) * 256 + lane * 4], acc2f4(AL2, AH2));
    st4(&P[(n0 + 3) * 256 + lane * 4], acc2f4(AL3, AH3));
    st4(&P[(n0 + 0) * 256 + 128 + lane * 4], acc2f4(BL0, BH0));
    st4(&P[(n0 + 1) * 256 + 128 + lane * 4], acc2f4(BL1, BH1));
    st4(&P[(n0 + 2) * 256 + 128 + lane * 4], acc2f4(BL2, BH2));
    st4(&P[(n0 + 3) * 256 + 128 + lane * 4], acc2f4(BL3, BH3));
}

// ---------------------------------------------------------------------------
// Per-edge predictor epilogue: out[e] = elu(A[src]+B[dst]+bp1) . Wp2 + bp2
// ---------------------------------------------------------------------------
__global__ void k_prededge(const float* __restrict__ P, const int* __restrict__ ei,
                           const float* __restrict__ bp1, const float* __restrict__ Wp2,
                           const float* __restrict__ bp2, float* __restrict__ out)
{
    int warp = (blockIdx.x * blockDim.x + threadIdx.x) >> 5;
    int lane = threadIdx.x & 31;
    int e0 = warp * 4;
    if (e0 >= N_EDGES_) return;

    float4 bv = ld4(&bp1[lane * 4]);
    float4 w2 = ld4(&Wp2[lane * 4]);
    float c = bp2[0];

    #pragma unroll
    for (int n = 0; n < 4; n++) {
        int e = e0 + n;
        int src = ei[e];
        int dst = ei[N_EDGES_ + e];
        float4 a = ld4(&P[src * 256 + lane * 4]);
        float4 b = ld4(&P[dst * 256 + 128 + lane * 4]);
        float4 t;
        t.x = eluf(a.x + b.x + bv.x);
        t.y = eluf(a.y + b.y + bv.y);
        t.z = eluf(a.z + b.z + bv.z);
        t.w = eluf(a.w + b.w + bv.w);
        float p = t.x * w2.x + t.y * w2.y + t.z * w2.z + t.w * w2.w;
        #pragma unroll
        for (int off = 16; off; off >>= 1)
            p += __shfl_xor_sync(0xffffffffu, p, off);
        if (lane == 0) out[e] = p + c;
    }
}

// ---------------------------------------------------------------------------
extern "C" void kernel_launch(void* const* d_in, const int* in_sizes, int n_in,
                              void* d_out, int out_size)
{
    const float* x    = (const float*)d_in[0];
    const int*   ei   = (const int*)  d_in[1];
    const float* ea   = (const float*)d_in[2];
    const float* We0  = (const float*)d_in[3];
    const float* be0  = (const float*)d_in[4];
    const float* W10  = (const float*)d_in[5];
    const float* b10  = (const float*)d_in[6];
    const float* W20  = (const float*)d_in[7];
    const float* b20  = (const float*)d_in[8];
    const float* We_s = (const float*)d_in[9];
    const float* be_s = (const float*)d_in[10];
    const float* W1_s = (const float*)d_in[11];
    const float* b1_s = (const float*)d_in[12];
    const float* W2_s = (const float*)d_in[13];
    const float* b2_s = (const float*)d_in[14];
    const float* Wp1  = (const float*)d_in[15];
    const float* bp1  = (const float*)d_in[16];
    const float* Wp2  = (const float*)d_in[17];
    const float* bp2  = (const float*)d_in[18];
    float* out = (float*)d_out;

    float *hA, *hB, *P;
    int *deg;
    cudaGetSymbolAddress((void**)&hA, g_h);
    cudaGetSymbolAddress((void**)&hB, g_hn);
    cudaGetSymbolAddress((void**)&P,  g_P);
    cudaGetSymbolAddress((void**)&deg, g_deg);

    // ---- CSR build ----
    cudaMemsetAsync(deg, 0, N_NODES_ * sizeof(int));
    k_hist <<<(N_EDGES_ + 255) / 256, 256>>>(ei);
    k_scanA<<<NBLK_, SCAN_B>>>();
    k_scanB<<<1, 128>>>();
    k_scanC<<<NBLK_, SCAN_B>>>();
    k_fill <<<(N_EDGES_ + 255) / 256, 256>>>(ei, ea);

    // ---- Layer 0 (16 -> 128) ----
    k_aggr0<<<(N_NODES_ * 16 + 255) / 256, 256>>>(x, We0, be0, P);   // reuse P as aggr16
    node_mlp16<<<N_NODES_ / 32, 256>>>(x, P, W10, b10, W20, b20, hA);

    // ---- Layers 1..4 ----
    for (int l = 0; l < 4; l++) {
        gine_layer<<<N_NODES_ / 32, 256>>>(hA,
                                           We_s + l * HID_, be_s + l * HID_,
                                           W1_s + l * HID_ * HID_, b1_s + l * HID_,
                                           W2_s + l * HID_ * HID_, b2_s + l * HID_, hB);
        float* t = hA; hA = hB; hB = t;
    }

    // ---- Edge predictor ----
    k_prednode<<<N_NODES_ / 32, 256>>>(hA, Wp1, P);
    k_prededge<<<(N_EDGES_ / 4 * 32 + 255) / 256, 256>>>(P, ei, bp1, Wp2, bp2, out);
}